// round 16
// baseline (speedup 1.0000x reference)
#include <cuda_runtime.h>
#include <cuda_fp16.h>

// EGCL_Multi — sm_103. R13: (1) T0's rank-8 GEMM moved to tensor cores with
// hi/lo split fp16 (error-free); (2) per-chunk __syncthreads replaced with
// empty-mbarrier producer backpressure (one barrier per layer remains).
// MMA math otherwise identical to R12: l0 fp16 k16 f32acc, l1/l2 fp8 k32.
#define NN 512

__device__ __align__(16) float g_hc[NN * 192];
__device__ __align__(16) float g_A[NN * 256];
__device__ __align__(16) float g_B[NN * 256];
__device__ __align__(16) float g_mi[NN * 256];
__device__ __align__(16) float g_shift[NN * 24];
// chunks 0-3: fp16 We1 32KB each; chunks 4-11: fp8 Wx0/Wx1 16KB each @131072
__device__ __align__(128) char g_Wstage[262144];

// ---------------- small helpers ----------------
__device__ __forceinline__ float silu_f(float v) {
    return v * (1.0f / (1.0f + __expf(-v)));
}
__device__ __forceinline__ unsigned smem_u32(const void* p) {
    unsigned a;
    asm("{ .reg .u64 t; cvta.to.shared.u64 t, %1; cvt.u32.u64 %0, t; }"
        : "=r"(a) : "l"(p));
    return a;
}
__device__ __forceinline__ void sts32(unsigned addr, unsigned v) {
    asm volatile("st.shared.b32 [%0], %1;" :: "r"(addr), "r"(v) : "memory");
}
__device__ __forceinline__ void sts16(unsigned addr, unsigned short v) {
    asm volatile("st.shared.u16 [%0], %1;" :: "r"(addr), "h"(v) : "memory");
}
__device__ __forceinline__ void ldmat4(unsigned* r, unsigned addr) {
    asm volatile(
        "ldmatrix.sync.aligned.m8n8.x4.shared.b16 {%0,%1,%2,%3}, [%4];"
        : "=r"(r[0]), "=r"(r[1]), "=r"(r[2]), "=r"(r[3]) : "r"(addr));
}
__device__ __forceinline__ void cp16(unsigned dst, const void* src) {
    asm volatile("cp.async.ca.shared.global [%0], [%1], 16;"
                 :: "r"(dst), "l"(src) : "memory");
}
#define CP_COMMIT() asm volatile("cp.async.commit_group;" ::: "memory")
#define CP_WAIT1() asm volatile("cp.async.wait_group 1;" ::: "memory")
#define CP_WAIT0() asm volatile("cp.async.wait_group 0;" ::: "memory")
#define MBAR_INIT(mb, n) \
    asm volatile("mbarrier.init.shared.b64 [%0], %1;" :: "r"(mb), "r"(n) : "memory")
#define MBAR_ARRIVE(mb) \
    asm volatile("mbarrier.arrive.shared.b64 _, [%0];" :: "r"(mb) : "memory")
#define EXPECT_TX(mb, n) \
    asm volatile("mbarrier.arrive.expect_tx.shared.b64 _, [%0], %1;" \
                 :: "r"(mb), "r"(n) : "memory")
__device__ __forceinline__ void mbar_wait(unsigned mb, unsigned par) {
    asm volatile(
        "{\n\t.reg .pred P;\n"
        "WL_%=:\n\t"
        "mbarrier.try_wait.parity.acquire.cta.shared::cta.b64 P, [%0], %1, 0x989680;\n\t"
        "@P bra.uni WD_%=;\n\tbra.uni WL_%=;\nWD_%=:\n\t}"
        :: "r"(mb), "r"(par) : "memory");
}
__device__ __forceinline__ void bulk_cp(unsigned dst, const void* src, unsigned bytes,
                                        unsigned mbar) {
    asm volatile(
        "cp.async.bulk.shared::cluster.global.mbarrier::complete_tx::bytes "
        "[%0], [%1], %2, [%3];"
        :: "r"(dst), "l"(src), "r"(bytes), "r"(mbar) : "memory");
}
__device__ __forceinline__ unsigned hpack2(float a, float b) {
    __half2 h = __floats2half2_rn(a, b);
    return *(unsigned*)&h;
}
__device__ __forceinline__ unsigned short f8pack2(float lo, float hi) {
    unsigned short q;
    asm("cvt.rn.satfinite.e4m3x2.f32 %0, %1, %2;" : "=h"(q) : "f"(hi), "f"(lo));
    return q;
}
__device__ __forceinline__ void mma16816(float* d, const unsigned* a, unsigned b0,
                                         unsigned b1) {
    asm volatile(
        "mma.sync.aligned.m16n8k16.row.col.f32.f16.f16.f32 "
        "{%0,%1,%2,%3}, {%4,%5,%6,%7}, {%8,%9}, {%0,%1,%2,%3};"
        : "+f"(d[0]), "+f"(d[1]), "+f"(d[2]), "+f"(d[3])
        : "r"(a[0]), "r"(a[1]), "r"(a[2]), "r"(a[3]), "r"(b0), "r"(b1));
}
__device__ __forceinline__ void mma16832f8(float* d, const unsigned* a, unsigned b0,
                                           unsigned b1) {
    asm volatile(
        "mma.sync.aligned.m16n8k32.row.col.f32.e4m3.e4m3.f32 "
        "{%0,%1,%2,%3}, {%4,%5,%6,%7}, {%8,%9}, {%0,%1,%2,%3};"
        : "+f"(d[0]), "+f"(d[1]), "+f"(d[2]), "+f"(d[3])
        : "r"(a[0]), "r"(a[1]), "r"(a[2]), "r"(a[3]), "r"(b0), "r"(b1));
}

// ---------------- f32x2 SIMT gemm (node-side) ----------------
__device__ __forceinline__ unsigned long long pk2(float lo, float hi) {
    unsigned long long r;
    asm("mov.b64 %0, {%1, %2};" : "=l"(r) : "f"(lo), "f"(hi));
    return r;
}
__device__ __forceinline__ void upk2(unsigned long long v, float& lo, float& hi) {
    asm("mov.b64 {%0, %1}, %2;" : "=f"(lo), "=f"(hi) : "l"(v));
}
__device__ __forceinline__ void fma2(unsigned long long& d, unsigned long long a,
                                     unsigned long long b) {
    asm("fma.rn.f32x2 %0, %1, %2, %0;" : "+l"(d) : "l"(a), "l"(b));
}
template <int ROWS, int N, bool ACT>
__device__ __forceinline__ void gemmR(const float* sIn, int K,
                                      const float* __restrict__ Wg, int wstride,
                                      const float* __restrict__ bias, float* out,
                                      int ostride, float* ws) {
    constexpr int COLG = N / 8;
    constexpr int RPT = ROWS * COLG / 256;
    const int t = threadIdx.x;
    const int nc = t % COLG, mr = t / COLG;
    const int r0 = mr * RPT, c0 = nc * 8;
    const int R = K / 32;
    unsigned long long acc[RPT][4];
#pragma unroll
    for (int r = 0; r < RPT; r++)
#pragma unroll
        for (int p = 0; p < 4; p++) acc[r][p] = 0ULL;

    const unsigned wsb = smem_u32(ws);
    for (int idx = t; idx < 32 * N / 4; idx += 256) {
        int wr = idx / (N / 4), wc = (idx - wr * (N / 4)) * 4;
        cp16(wsb + (unsigned)((wr * N + wc) * 4), &Wg[wr * wstride + wc]);
    }
    CP_COMMIT();

    for (int r = 0; r < R; ++r) {
        if (r + 1 < R) {
            unsigned dstb = wsb + (unsigned)(((r + 1) & 1) * 32 * N * 4);
            const float* src = Wg + (r + 1) * 32 * wstride;
            for (int idx = t; idx < 32 * N / 4; idx += 256) {
                int wr = idx / (N / 4), wc = (idx - wr * (N / 4)) * 4;
                cp16(dstb + (unsigned)((wr * N + wc) * 4), &src[wr * wstride + wc]);
            }
            CP_COMMIT();
            CP_WAIT1();
        } else {
            CP_WAIT0();
        }
        __syncthreads();
        const float* wb = ws + (r & 1) * 32 * N;
        const int kt = r * 32;
#pragma unroll
        for (int k4 = 0; k4 < 8; k4++) {
            float4 av[RPT];
#pragma unroll
            for (int rr = 0; rr < RPT; rr++)
                av[rr] = *(const float4*)&sIn[(r0 + rr) * K + kt + k4 * 4];
#pragma unroll
            for (int kk = 0; kk < 4; kk++) {
                const float* wr_ = &wb[(k4 * 4 + kk) * N + c0];
                float4 w0 = *(const float4*)&wr_[0];
                float4 w1 = *(const float4*)&wr_[4];
                unsigned long long b0 = pk2(w0.x, w0.y), b1 = pk2(w0.z, w0.w);
                unsigned long long b2 = pk2(w1.x, w1.y), b3 = pk2(w1.z, w1.w);
#pragma unroll
                for (int rr = 0; rr < RPT; rr++) {
                    float a = (kk == 0) ? av[rr].x : (kk == 1) ? av[rr].y
                            : (kk == 2) ? av[rr].z : av[rr].w;
                    unsigned long long a2 = pk2(a, a);
                    fma2(acc[rr][0], a2, b0);
                    fma2(acc[rr][1], a2, b1);
                    fma2(acc[rr][2], a2, b2);
                    fma2(acc[rr][3], a2, b3);
                }
            }
        }
        __syncthreads();
    }
#pragma unroll
    for (int rr = 0; rr < RPT; rr++)
#pragma unroll
        for (int p = 0; p < 4; p++) {
            float lo, hi;
            upk2(acc[rr][p], lo, hi);
            int c = c0 + p * 2;
            if (bias) {
                float2 bb = *(const float2*)&bias[c];
                lo += bb.x;
                hi += bb.y;
            }
            if (ACT) { lo = silu_f(lo); hi = silu_f(hi); }
            float2 o; o.x = lo; o.y = hi;
            *(float2*)&out[(r0 + rr) * ostride + c] = o;
        }
    __syncthreads();
}

// ---------------- prep kernels ----------------
__global__ void prep_hc(const float* __restrict__ x, const float* __restrict__ h) {
    int n = blockIdx.x, t = threadIdx.x;
    if (t < 128) g_hc[n * 192 + t] = h[n * 128 + t];
    else if (t < 192) {
        int p = t - 128, a = p >> 3, b = p & 7;
        float dx = x[n * 24 + a * 3] - x[n * 24 + b * 3];
        float dy = x[n * 24 + a * 3 + 1] - x[n * 24 + b * 3 + 1];
        float dz = x[n * 24 + a * 3 + 2] - x[n * 24 + b * 3 + 2];
        g_hc[n * 192 + 128 + p] = dx * dx + dy * dy + dz * dz;
    }
    g_mi[n * 256 + t] = 0.f;
    if (t < 24) g_shift[n * 24 + t] = 0.f;
}
__global__ void prep_w(const float* __restrict__ We1, const float* __restrict__ Wx0,
                       const float* __restrict__ Wx1) {
    __shared__ float tile[32][33];
    int sel = blockIdx.z;
    const float* W = (sel == 0) ? We1 : (sel == 1) ? Wx0 : Wx1;
    int n0 = blockIdx.x * 32, k0 = blockIdx.y * 32;
    int tx = threadIdx.x, ty = threadIdx.y;
    for (int r = ty; r < 32; r += 8) tile[r][tx] = W[(k0 + r) * 256 + n0 + tx];
    __syncthreads();
    for (int r = ty; r < 32; r += 8) {
        float v = tile[tx][r];  // = W[k0+tx][n0+r]
        int n = n0 + r, k = k0 + tx;
        int chunk = k >> 6, kin = k & 63;
        if (sel == 0) {
            unsigned off = (unsigned)(chunk * 32768 + n * 128 +
                                      (((kin >> 3) * 16) ^ ((n & 7) * 16)) +
                                      (kin & 7) * 2);
            *(__half*)(g_Wstage + off) = __float2half_rn(v);
        } else {
            unsigned u = (unsigned)((kin >> 4) ^ ((n >> 1) & 3));
            unsigned off = (unsigned)(131072 + ((sel - 1) * 4 + chunk) * 16384 +
                                      n * 64 + u * 16 + (kin & 15));
            g_Wstage[off] = (char)(f8pack2(v, 0.f) & 0xff);
        }
    }
}
__global__ void __launch_bounds__(256) prep_ab(const float* __restrict__ We0) {
    extern __shared__ float sm[];
    float* sIn = sm;              // 16*192
    float* ws = sm + 16 * 192;    // 2*32*128
    int r0g = blockIdx.x * 16, t = threadIdx.x;
    int sel = blockIdx.y, nh = blockIdx.z;
    for (int idx = t; idx < 16 * 192 / 4; idx += 256)
        *(float4*)&sIn[idx * 4] = *(const float4*)&g_hc[r0g * 192 + idx * 4];
    __syncthreads();
    const float* Wg = We0 + (sel == 0 ? 8 : 200) * 256 + nh * 128;
    float* outp = (sel == 0 ? g_A : g_B) + r0g * 256 + nh * 128;
    gemmR<16, 128, false>(sIn, 192, Wg, 256, nullptr, outp, 256, ws);
}

// ---------------- edge kernel ----------------
#define OFF_A 0          // 33792 (fp16 plane: 64 rows x 264 halves)
#define OFF_W 33792      // l0: 2x32KB fp16 bufs; l>=1: 2x16KB fp8 bufs
#define OFF_A8 66560     // fp8 act plane (64 x 272B) — aliases buf1 after l0
// T0 staging (aliases buf1; dead after T0-MMA):
#define OFF_WEHI 66560   // 256 rows x 48B (k0-15 fp16 hi)
#define OFF_WELO 78848   // 256 rows x 48B (lo)
#define OFF_SQHI 91136   // 64 rows x 48B
#define OFF_SQLO 94208   // 64 rows x 48B
#define OFF_XJ 99328     // 6144
#define OFF_SQN 105472   // 2048
#define OFF_BI 107520    // 1024 (T0 only; aliased by PX later)
#define OFF_WINF 108544  // 1024 (l0 only; aliased by PX later)
#define OFF_PX OFF_BI    // 2048 (l2 only)
#define OFF_BIAS 109568  // 3072
#define OFF_PE 112640    // 256
#define OFF_E 112896     // 256
#define OFF_XI 113152    // 128
#define OFF_SH 113280    // 128
#define OFF_MB 113408    // 32: full0, full1, empty0, empty1
#define EDGE_SMEM 113440

__global__ void __launch_bounds__(256, 2) edge_kernel(
    const float* __restrict__ x, const float* __restrict__ We0,
    const float* __restrict__ be0, const float* __restrict__ be1,
    const float* __restrict__ Winf, const float* __restrict__ binf,
    const float* __restrict__ bx0, const float* __restrict__ bx1,
    const float* __restrict__ bxo, const float* __restrict__ Wxo) {
    extern __shared__ char smc[];
    const unsigned sb = smem_u32(smc);
    const int t = threadIdx.x;
    const int lane = t & 31, w = t >> 5;
    const int band = w >> 1, ng = w & 1;
    const int r0 = band * 16 + (lane >> 2);
    const int k4 = lane & 3;
    const int i = blockIdx.y, j0 = blockIdx.x * 64;

    // ldmatrix lane decode
    const int q = lane >> 3, qr = lane & 7;
    const unsigned aRow = (unsigned)(band * 16 + (q & 1) * 8 + qr);
    const unsigned aBase16 = sb + OFF_A + aRow * 528 + (unsigned)((q >> 1) * 16);
    const unsigned aBase8 = sb + OFF_A8 + aRow * 272 + (unsigned)((q >> 1) * 16);
    const int subAdd = q >> 1, hs = q & 1;
    const unsigned bn = (unsigned)(ng * 128 + subAdd * 8 + qr);
    const unsigned bkey16 = (unsigned)(qr * 16);

    float* sXj = (float*)(smc + OFF_XJ);
    float* sSqn = (float*)(smc + OFF_SQN);
    float* sBi = (float*)(smc + OFF_BI);
    float* sWinf = (float*)(smc + OFF_WINF);
    float* sBias = (float*)(smc + OFF_BIAS);
    float* sPE = (float*)(smc + OFF_PE);
    float* sE = (float*)(smc + OFF_E);
    float* sPx = (float*)(smc + OFF_PX);
    float* sXi = (float*)(smc + OFF_XI);
    float* sSh = (float*)(smc + OFF_SH);
    const unsigned mb0 = sb + OFF_MB, mb1 = sb + OFF_MB + 8;
    const unsigned me0 = sb + OFF_MB + 16, me1 = sb + OFF_MB + 24;

    if (t == 0) {
        MBAR_INIT(mb0, 1); MBAR_INIT(mb1, 1);
        MBAR_INIT(me0, 8); MBAR_INIT(me1, 8);
    }
    for (int idx = t; idx < 1536; idx += 256) sXj[idx] = x[j0 * 24 + idx];
    sBi[t] = g_B[i * 256 + t] + be0[t];
    sWinf[t] = Winf[t];
    sBias[t] = be1[t];
    sBias[256 + t] = bx0[t];
    sBias[512 + t] = bx1[t];
    if (t < 64) sPE[t] = 0.f;
    if (t < 24) { sXi[t] = x[i * 24 + t]; sSh[t] = 0.f; }
    // zero k8-15 halves of T0 staging planes (bytes 16..31 of each row)
    for (int idx = t; idx < 1024; idx += 256) {
        unsigned o = (unsigned)((idx >> 2) * 48 + 16 + (idx & 3) * 4);
        sts32(sb + OFF_WEHI + o, 0u);
        sts32(sb + OFF_WELO + o, 0u);
        if (idx < 256) {
            sts32(sb + OFF_SQHI + o, 0u);
            sts32(sb + OFF_SQLO + o, 0u);
        }
    }
    // stage We0[0:8] hi/lo fp16 (thread t = column n)
    {
        unsigned hh[4], ll[4];
#pragma unroll
        for (int p = 0; p < 4; ++p) {
            float w0 = __ldg(&We0[(2 * p) * 256 + t]);
            float w1 = __ldg(&We0[(2 * p + 1) * 256 + t]);
            unsigned hp = hpack2(w0, w1);
            float h0 = __half2float(*(__half*)&hp);
            float h1 = __half2float(((__half2*)&hp)->y);
            hh[p] = hp;
            ll[p] = hpack2(w0 - h0, w1 - h1);
        }
#pragma unroll
        for (int p = 0; p < 4; ++p) {
            sts32(sb + OFF_WEHI + (unsigned)(t * 48 + p * 4), hh[p]);
            sts32(sb + OFF_WELO + (unsigned)(t * 48 + p * 4), ll[p]);
        }
    }
    __syncthreads();

    if (t == 0) {  // kick chunk 0 (buf0)
        EXPECT_TX(mb0, 32768u);
        bulk_cp(sb + OFF_W, g_Wstage, 32768u, mb0);
    }

    // sqn (f32 for shift) + hi/lo fp16 staging for T0-MMA
    for (int p = t; p < 512; p += 256) {
        int j = p >> 3, hh = p & 7;
        float dx = sXj[j * 24 + hh * 3] - sXi[hh * 3];
        float dy = sXj[j * 24 + hh * 3 + 1] - sXi[hh * 3 + 1];
        float dz = sXj[j * 24 + hh * 3 + 2] - sXi[hh * 3 + 2];
        float s = dx * dx + dy * dy + dz * dz;
        sSqn[p] = s;
        __half sh = __float2half_rn(s);
        sts16(sb + OFF_SQHI + (unsigned)(j * 48 + hh * 2), __half_as_ushort(sh));
        sts16(sb + OFF_SQLO + (unsigned)(j * 48 + hh * 2),
              __half_as_ushort(__float2half_rn(s - __half2float(sh))));
    }
    __syncthreads();

    const float binf0 = binf[0];

    // ---- T0 via MMA: acc = sqn @ We0[0:8]  (hi/lo 3-product, exact) ----
    {
        float acc[16][4];
#pragma unroll
        for (int s2 = 0; s2 < 16; ++s2)
#pragma unroll
            for (int qq = 0; qq < 4; ++qq) acc[s2][qq] = 0.f;
        unsigned aH[4], aL[4];
        unsigned aAd = sb + OFF_SQHI + aRow * 48 + (unsigned)((q >> 1) * 16);
        ldmat4(aH, aAd);
        ldmat4(aL, aAd + (OFF_SQLO - OFF_SQHI));
#pragma unroll
        for (int s = 0; s < 16; s += 2) {
            unsigned bAd = sb + OFF_WEHI +
                           (unsigned)((ng * 128 + (s + subAdd) * 8 + qr) * 48 + hs * 16);
            unsigned bh[4], bl[4];
            ldmat4(bh, bAd);
            ldmat4(bl, bAd + (OFF_WELO - OFF_WEHI));
            mma16816(acc[s], aH, bh[0], bh[1]);
            mma16816(acc[s], aH, bl[0], bl[1]);
            mma16816(acc[s], aL, bh[0], bh[1]);
            mma16816(acc[s + 1], aH, bh[2], bh[3]);
            mma16816(acc[s + 1], aH, bl[2], bl[3]);
            mma16816(acc[s + 1], aL, bh[2], bh[3]);
        }
        __syncthreads();  // all warps done reading T0 staging (buf1)
        if (t == 0) {     // kick chunk 1 into buf1
            EXPECT_TX(mb1, 32768u);
            bulk_cp(sb + OFF_W + 32768u, g_Wstage + 32768, 32768u, mb1);
        }
        // epilogue: T0 = silu(acc + A[j] + (B[i]+be0)) -> fp16 plane
#pragma unroll
        for (int sub = 0; sub < 16; ++sub) {
            int col = ng * 128 + sub * 8 + k4 * 2;
            float2 gA0 = *(const float2*)&g_A[(j0 + r0) * 256 + col];
            float2 gA1 = *(const float2*)&g_A[(j0 + r0 + 8) * 256 + col];
            float2 bi = *(const float2*)&sBi[col];
            float v0 = silu_f(acc[sub][0] + gA0.x + bi.x);
            float v1 = silu_f(acc[sub][1] + gA0.y + bi.y);
            float v2 = silu_f(acc[sub][2] + gA1.x + bi.x);
            float v3 = silu_f(acc[sub][3] + gA1.y + bi.y);
            unsigned off = (unsigned)(r0 * 528 + col * 2);
            sts32(sb + OFF_A + off, hpack2(v0, v1));
            sts32(sb + OFF_A + off + 8 * 528, hpack2(v2, v3));
        }
    }
    __syncthreads();  // fp16 plane ready for l0 MMA

    for (int l = 0; l < 3; ++l) {
        float accf[16][4];
#pragma unroll
        for (int s2 = 0; s2 < 16; ++s2)
#pragma unroll
            for (int qq = 0; qq < 4; ++qq) accf[s2][qq] = 0.f;

        for (int c = 0; c < 4; ++c) {
            int g = l * 4 + c;
            int gn = g + 1;
            if (gn >= 2 && gn < 12 && t == 0) {
                // wait for all warps to release the target buffer (chunk gn-2)
                mbar_wait((gn & 1) ? me1 : me0, ((gn >> 1) + 1) & 1);
                unsigned mb = (gn & 1) ? mb1 : mb0;
                if (gn < 4) {
                    EXPECT_TX(mb, 32768u);
                    bulk_cp(sb + OFF_W + (unsigned)((gn & 1) * 32768),
                            g_Wstage + gn * 32768, 32768u, mb);
                } else {
                    EXPECT_TX(mb, 16384u);
                    bulk_cp(sb + OFF_W + (unsigned)((gn & 1) * 16384),
                            g_Wstage + 131072 + (gn - 4) * 16384, 16384u, mb);
                }
            }
            mbar_wait((g & 1) ? mb1 : mb0, (g >> 1) & 1);
            if (l == 0) {
                const unsigned wb = sb + OFF_W + (unsigned)((g & 1) * 32768);
#pragma unroll
                for (int ks = 0; ks < 4; ++ks) {
                    unsigned ah[4];
                    ldmat4(ah, aBase16 + (unsigned)(c * 128 + ks * 32));
                    unsigned xt = ((unsigned)(ks * 32 + hs * 16)) ^ bkey16;
                    unsigned bb = wb + bn * 128 + xt;
#pragma unroll
                    for (int s = 0; s < 16; s += 2) {
                        unsigned bm[4];
                        ldmat4(bm, bb + (unsigned)(s * 1024));
                        mma16816(accf[s], ah, bm[0], bm[1]);
                        mma16816(accf[s + 1], ah, bm[2], bm[3]);
                    }
                }
            } else {
                const unsigned wb = sb + OFF_W + (unsigned)((g & 1) * 16384);
#pragma unroll
                for (int ks = 0; ks < 2; ++ks) {
                    unsigned ah[4];
                    ldmat4(ah, aBase8 + (unsigned)(c * 64 + ks * 32));
                    unsigned kx = (unsigned)(ks * 2 + hs);
#pragma unroll
                    for (int s = 0; s < 16; s += 2) {
                        unsigned n = bn + (unsigned)(s * 8);
                        unsigned addr = wb + n * 64 + ((kx ^ ((n >> 1) & 3u)) * 16u);
                        unsigned bm[4];
                        ldmat4(bm, addr);
                        mma16832f8(accf[s], ah, bm[0], bm[1]);
                        mma16832f8(accf[s + 1], ah, bm[2], bm[3]);
                    }
                }
            }
            if (lane == 0) MBAR_ARRIVE((g & 1) ? me1 : me0);
        }
        __syncthreads();  // layer end: all MMA reads done before plane writes

        // ---------------- epilogues ----------------
        if (l == 0) {
            float pe0 = 0.f, pe1 = 0.f;
#pragma unroll
            for (int sub = 0; sub < 16; ++sub) {
                int col = ng * 128 + sub * 8 + k4 * 2;
                float v0 = silu_f(accf[sub][0] + sBias[col]);
                float v1 = silu_f(accf[sub][1] + sBias[col + 1]);
                float v2 = silu_f(accf[sub][2] + sBias[col]);
                float v3 = silu_f(accf[sub][3] + sBias[col + 1]);
                pe0 += v0 * sWinf[col] + v1 * sWinf[col + 1];
                pe1 += v2 * sWinf[col] + v3 * sWinf[col + 1];
                unsigned off = (unsigned)(r0 * 528 + col * 2);
                sts32(sb + OFF_A + off, hpack2(v0, v1));
                sts32(sb + OFF_A + off + 8 * 528, hpack2(v2, v3));
                unsigned a8 = sb + OFF_A8 + (unsigned)(r0 * 272 + col);
                sts16(a8, f8pack2(v0, v1));
                sts16(a8 + 8 * 272, f8pack2(v2, v3));
            }
            pe0 += __shfl_xor_sync(0xffffffffu, pe0, 1);
            pe0 += __shfl_xor_sync(0xffffffffu, pe0, 2);
            pe1 += __shfl_xor_sync(0xffffffffu, pe1, 1);
            pe1 += __shfl_xor_sync(0xffffffffu, pe1, 2);
            if (k4 == 0) {
                atomicAdd(&sPE[r0], pe0);
                atomicAdd(&sPE[r0 + 8], pe1);
            }
            __syncthreads();
            if (t < 64) {
                float z = sPE[t] + binf0;
                float e = 1.0f / (1.0f + __expf(-z));
                if (j0 + t == i) e = 0.f;
                sE[t] = e;
            }
            __syncthreads();
            {
                const __half* mh = (const __half*)(smc + OFF_A);
                float a_ = 0.f;
#pragma unroll 4
                for (int j = 0; j < 64; ++j)
                    a_ += __half2float(mh[j * 264 + t]) * sE[j];
                atomicAdd(&g_mi[i * 256 + t], a_);
            }
        } else if (l == 1) {
#pragma unroll
            for (int sub = 0; sub < 16; ++sub) {
                int col = ng * 128 + sub * 8 + k4 * 2;
                float v0 = silu_f(accf[sub][0] + sBias[256 + col]);
                float v1 = silu_f(accf[sub][1] + sBias[256 + col + 1]);
                float v2 = silu_f(accf[sub][2] + sBias[256 + col]);
                float v3 = silu_f(accf[sub][3] + sBias[256 + col + 1]);
                unsigned a8 = sb + OFF_A8 + (unsigned)(r0 * 272 + col);
                sts16(a8, f8pack2(v0, v1));
                sts16(a8 + 8 * 272, f8pack2(v2, v3));
            }
            for (int p = t; p < 512; p += 256) sPx[p] = 0.f;
        } else {
            float* sWxo = (float*)(smc + OFF_A);
            for (int idx = t; idx < 2048; idx += 256) sWxo[idx] = Wxo[idx];
            __syncthreads();
            float pxa0[8], pxa1[8];
#pragma unroll
            for (int hh = 0; hh < 8; ++hh) { pxa0[hh] = 0.f; pxa1[hh] = 0.f; }
#pragma unroll
            for (int sub = 0; sub < 16; ++sub) {
                int col = ng * 128 + sub * 8 + k4 * 2;
                float v0 = silu_f(accf[sub][0] + sBias[512 + col]);
                float v1 = silu_f(accf[sub][1] + sBias[512 + col + 1]);
                float v2 = silu_f(accf[sub][2] + sBias[512 + col]);
                float v3 = silu_f(accf[sub][3] + sBias[512 + col + 1]);
                const float* w0 = &sWxo[col * 8];
                const float* w1 = &sWxo[(col + 1) * 8];
#pragma unroll
                for (int hh = 0; hh < 8; ++hh) {
                    pxa0[hh] += v0 * w0[hh] + v1 * w1[hh];
                    pxa1[hh] += v2 * w0[hh] + v3 * w1[hh];
                }
            }
#pragma unroll
            for (int hh = 0; hh < 8; ++hh) {
                pxa0[hh] += __shfl_xor_sync(0xffffffffu, pxa0[hh], 1);
                pxa0[hh] += __shfl_xor_sync(0xffffffffu, pxa0[hh], 2);
                pxa1[hh] += __shfl_xor_sync(0xffffffffu, pxa1[hh], 1);
                pxa1[hh] += __shfl_xor_sync(0xffffffffu, pxa1[hh], 2);
            }
            if (k4 == 0) {
#pragma unroll
                for (int hh = 0; hh < 8; ++hh) {
                    atomicAdd(&sPx[r0 * 8 + hh], pxa0[hh]);
                    atomicAdd(&sPx[(r0 + 8) * 8 + hh], pxa1[hh]);
                }
            }
            __syncthreads();
            for (int p = t; p < 512; p += 256) {
                int j = p >> 3, hh = p & 7;
                float px = sPx[p] + bxo[hh];
                if (j0 + j == i) px = 0.f;
                float nrm = sqrtf(sSqn[p] + 1e-8f) + 1.0f;
                float wgt = px / nrm;
#pragma unroll
                for (int d = 0; d < 3; ++d)
                    atomicAdd(&sSh[hh * 3 + d],
                              wgt * (sXj[j * 24 + hh * 3 + d] - sXi[hh * 3 + d]));
            }
            __syncthreads();
            if (t < 24) atomicAdd(&g_shift[i * 24 + t], sSh[t]);
        }
        __syncthreads();
    }
}

// ---------------- node kernels ----------------
__global__ void __launch_bounds__(256) hnew_kernel(
    const float* __restrict__ h, const float* __restrict__ Wh0,
    const float* __restrict__ bh0, const float* __restrict__ Wh1,
    const float* __restrict__ bh1, const float* __restrict__ Who,
    const float* __restrict__ bho, float* __restrict__ out) {
    extern __shared__ float sm[];
    float* buf0 = sm;                 // 16*384
    float* buf1 = buf0 + 16 * 384;    // 16*256
    float* ws = buf1 + 16 * 256;      // 2*32*256
    int r0g = blockIdx.x * 16, t = threadIdx.x;
    for (int idx = t; idx < 16 * 384; idx += 256) {
        int row = idx / 384, c = idx - row * 384;
        buf0[idx] = (c < 256) ? g_mi[(r0g + row) * 256 + c]
                              : h[(r0g + row) * 128 + (c - 256)];
    }
    __syncthreads();
    gemmR<16, 256, true>(buf0, 384, Wh0, 256, bh0, buf1, 256, ws);
    gemmR<16, 256, true>(buf1, 256, Wh1, 256, bh1, buf0, 256, ws);
    gemmR<16, 128, false>(buf0, 256, Who, 128, bho, buf1, 128, ws);
    for (int idx = t; idx < 16 * 128; idx += 256)
        out[r0g * 128 + idx] = buf1[idx] + h[r0g * 128 + idx];
}
__global__ void xnew_kernel(const float* __restrict__ x, float* __restrict__ out) {
    int idx = blockIdx.x * 256 + threadIdx.x;
    if (idx < NN * 24) out[idx] = x[idx] + g_shift[idx] * (1.0f / 511.0f);
}

// ---------------- launch ----------------
extern "C" void kernel_launch(void* const* d_in, const int* in_sizes, int n_in,
                              void* d_out, int out_size) {
    const float* x = (const float*)d_in[0];
    const float* h = (const float*)d_in[1];
    const float* We0 = (const float*)d_in[2];
    const float* be0 = (const float*)d_in[3];
    const float* We1 = (const float*)d_in[4];
    const float* be1 = (const float*)d_in[5];
    const float* Winf = (const float*)d_in[6];
    const float* binf = (const float*)d_in[7];
    const float* Wx0 = (const float*)d_in[8];
    const float* bx0 = (const float*)d_in[9];
    const float* Wx1 = (const float*)d_in[10];
    const float* bx1 = (const float*)d_in[11];
    const float* Wxo = (const float*)d_in[12];
    const float* bxo = (const float*)d_in[13];
    const float* Wh0 = (const float*)d_in[14];
    const float* bh0 = (const float*)d_in[15];
    const float* Wh1 = (const float*)d_in[16];
    const float* bh1 = (const float*)d_in[17];
    const float* Who = (const float*)d_in[18];
    const float* bho = (const float*)d_in[19];
    float* out = (float*)d_out;  // [x_new (512*24) | h_new (512*128)]

    const int AB_SMEM = (16 * 192 + 2 * 32 * 128) * 4;
    const int HNEW_SMEM = (16 * 384 + 16 * 256 + 2 * 32 * 256) * 4;
    cudaFuncSetAttribute(edge_kernel, cudaFuncAttributeMaxDynamicSharedMemorySize,
                         EDGE_SMEM);
    cudaFuncSetAttribute(prep_ab, cudaFuncAttributeMaxDynamicSharedMemorySize, AB_SMEM);
    cudaFuncSetAttribute(hnew_kernel, cudaFuncAttributeMaxDynamicSharedMemorySize,
                         HNEW_SMEM);

    prep_hc<<<NN, 256>>>(x, h);
    prep_w<<<dim3(8, 8, 3), dim3(32, 8)>>>(We1, Wx0, Wx1);
    prep_ab<<<dim3(32, 2, 2), 256, AB_SMEM>>>(We0);
    edge_kernel<<<dim3(8, NN), 256, EDGE_SMEM>>>(x, We0, be0, be1, Winf, binf, bx0,
                                                 bx1, bxo, Wxo);
    hnew_kernel<<<32, 256, HNEW_SMEM>>>(h, Wh0, bh0, Wh1, bh1, Who, bho, out + NN * 24);
    xnew_kernel<<<48, 256>>>(x, out);
}